// round 6
// baseline (speedup 1.0000x reference)
#include <cuda_runtime.h>
#include <cstdint>

#define BATCH 4096
#define DIM 512
#define TWOB 8192
#define INV_TEMP 10.0f
#define QSCALE 480.0f
#define DEQ (INV_TEMP / (QSCALE * QSCALE))

// ---------------- scratch (no allocations allowed) ----------------
__device__ int8_t g_zq[(size_t)TWOB * DIM];   // quantized normalized rows [8192,512] int8
__device__ float g_pos[BATCH];                // exact cos(n1_i, n2_i), fp32
__device__ float g_rowsum[TWOB];              // sum_{j!=i} exp(cos_ij/T)

// ---------------- helpers ----------------
__device__ __forceinline__ uint32_t smem_u32(const void* p) {
    uint32_t a;
    asm("{ .reg .u64 t; cvta.to.shared.u64 t, %1; cvt.u32.u64 %0, t; }" : "=r"(a) : "l"(p));
    return a;
}
__device__ __forceinline__ void cp16(uint32_t s, const void* g) {
    asm volatile("cp.async.cg.shared.global [%0], [%1], 16;" :: "r"(s), "l"(g) : "memory");
}
__device__ __forceinline__ void ldm_x4(uint32_t& r0, uint32_t& r1, uint32_t& r2, uint32_t& r3,
                                       uint32_t addr) {
    asm volatile("ldmatrix.sync.aligned.m8n8.x4.shared.b16 {%0,%1,%2,%3}, [%4];"
                 : "=r"(r0), "=r"(r1), "=r"(r2), "=r"(r3) : "r"(addr));
}
// int8 IMMA: m16n8k32, s32 accumulate. Fragments are byte-identical to the
// bf16 m16n8k16 fragments under a b16 reinterpretation of [16x32 s8] tiles,
// so the ldmatrix addressing below is unchanged from the proven bf16 path.
__device__ __forceinline__ void mma_s8(int* d, const uint32_t* a, const uint32_t* b) {
    asm volatile(
        "mma.sync.aligned.m16n8k32.row.col.s32.s8.s8.s32 "
        "{%0,%1,%2,%3}, {%4,%5,%6,%7}, {%8,%9}, {%0,%1,%2,%3};"
        : "+r"(d[0]), "+r"(d[1]), "+r"(d[2]), "+r"(d[3])
        : "r"(a[0]), "r"(a[1]), "r"(a[2]), "r"(a[3]), "r"(b[0]), "r"(b[1]));
}

// tile geometry (bytes: 1 int8 per element)
#define BM 128
#define BN 128
#define BKB 64                     // 64 int8 of k per stage
#define NSTEPS (DIM / BKB)         // 8
#define NT (TWOB / BM)             // 64 tile-rows
#define NTILES (NT * (NT + 1) / 2) // 2080 upper-triangle tiles
#define TILE_BYTES (BM * BKB)      // 8192 per operand tile
#define STAGE_BYTES (2 * TILE_BYTES)
#define NSTAGE 3

// swizzled byte offset inside a [rows x 64B] tile (4 x 16B chunks per row)
__device__ __forceinline__ uint32_t swz(int row, int chunk) {
    return (uint32_t)(row * 64 + ((chunk ^ ((row >> 1) & 3)) << 4));
}

// ============ Kernel A: L2-normalize, quantize to s8, positives, zero rowsums ============
__global__ void __launch_bounds__(128) k_norm(const float* __restrict__ p1,
                                              const float* __restrict__ p2) {
    const int i = blockIdx.x;
    const int t = threadIdx.x, w = t >> 5, l = t & 31;
    __shared__ float red[8];

    float4 a = ((const float4*)(p1 + (size_t)i * DIM))[t];
    float4 b = ((const float4*)(p2 + (size_t)i * DIM))[t];
    float sa = a.x * a.x + a.y * a.y + a.z * a.z + a.w * a.w;
    float sb = b.x * b.x + b.y * b.y + b.z * b.z + b.w * b.w;
#pragma unroll
    for (int o = 16; o; o >>= 1) {
        sa += __shfl_xor_sync(0xffffffffu, sa, o);
        sb += __shfl_xor_sync(0xffffffffu, sb, o);
    }
    if (!l) { red[w] = sa; red[4 + w] = sb; }
    __syncthreads();
    sa = red[0] + red[1] + red[2] + red[3];
    sb = red[4] + red[5] + red[6] + red[7];
    const float ra = rsqrtf(fmaxf(sa, 1e-24f));
    const float rb = rsqrtf(fmaxf(sb, 1e-24f));
    float4 na = make_float4(a.x * ra, a.y * ra, a.z * ra, a.w * ra);
    float4 nb = make_float4(b.x * rb, b.y * rb, b.z * rb, b.w * rb);
    float dp = na.x * nb.x + na.y * nb.y + na.z * nb.z + na.w * nb.w;
#pragma unroll
    for (int o = 16; o; o >>= 1) dp += __shfl_xor_sync(0xffffffffu, dp, o);
    __syncthreads();
    if (!l) red[w] = dp;
    __syncthreads();
    if (!t) {
        g_pos[i] = red[0] + red[1] + red[2] + red[3];   // exact positive cos
        g_rowsum[i] = 0.f;
        g_rowsum[BATCH + i] = 0.f;
    }
    auto q8 = [](float x) {
        return (char)__float2int_rn(fminf(fmaxf(x * QSCALE, -127.f), 127.f));
    };
    char4 qa, qb;
    qa.x = q8(na.x); qa.y = q8(na.y); qa.z = q8(na.z); qa.w = q8(na.w);
    qb.x = q8(nb.x); qb.y = q8(nb.y); qb.z = q8(nb.z); qb.w = q8(nb.w);
    ((char4*)(g_zq + (size_t)i * DIM))[t] = qa;
    ((char4*)(g_zq + (size_t)(BATCH + i) * DIM))[t] = qb;
}

// ============ Kernel B: persistent upper-triangle s8 GEMM + exp + row/col sums ============
// 128 threads = 4 warps in 2x2 grid, 64x64 warp tile. 2 CTAs/SM.
// Cross-tile prefetch: next tile's first 2 stages issued before the epilogue.
__global__ void __launch_bounds__(128, 2) k_sim() {
    __shared__ __align__(128) char smem[NSTAGE * STAGE_BYTES];  // 48 KB
    const uint32_t sbase = smem_u32(smem);

    const int tid = threadIdx.x;
    const int lane = tid & 31;
    const int wid = tid >> 5;
    const int warp_m = wid & 1;
    const int warp_n = wid >> 1;

    auto tile_of = [](int bid, int& ti, int& tj) {
        auto offs = [](int t) { return t * NT - (t * (t - 1)) / 2; };
        int x = (int)((2.f * NT + 1.f -
                       sqrtf((2.f * NT + 1.f) * (2.f * NT + 1.f) - 8.f * bid)) * 0.5f);
        if (x < 0) x = 0;
        if (x > NT - 1) x = NT - 1;
        while (offs(x + 1) <= bid) x++;
        while (offs(x) > bid) x--;
        ti = x;
        tj = x + (bid - offs(x));
    };

    auto load_stage = [&](const int8_t* pza, const int8_t* pzb, int kc, int buf) {
        const uint32_t sA = sbase + buf * STAGE_BYTES;
        const uint32_t sB = sA + TILE_BYTES;
#pragma unroll
        for (int it = 0; it < 8; it++) {
            int id = it * 128 + tid;
            int tile = id >> 9;
            int idx = id & 511;
            int row = idx >> 2, ch = idx & 3;
            const int8_t* g = (tile ? pzb : pza) + (size_t)row * DIM + kc * BKB + ch * 16;
            cp16((tile ? sB : sA) + swz(row, ch), g);
        }
        asm volatile("cp.async.commit_group;" ::: "memory");
    };

    // ldmatrix lane address components (b16-view; identical to bf16 path)
    const int a_row = warp_m * 64 + (lane & 15);
    const int a_chsel = lane >> 4;
    const int b_row = warp_n * 64 + (lane & 7) + ((lane >> 4) << 3);
    const int b_chsel = (lane >> 3) & 1;

    int pb = 0, gb = 0;  // put/get stage buffers (mod 3, continuous across tiles)
    int t = blockIdx.x;
    if (t >= NTILES) return;
    int ti, tj;
    tile_of(t, ti, tj);
    const int8_t* za = g_zq + (size_t)ti * BM * DIM;
    const int8_t* zb = g_zq + (size_t)tj * BN * DIM;
    load_stage(za, zb, 0, pb); pb = (pb == 2) ? 0 : pb + 1;
    load_stage(za, zb, 1, pb); pb = (pb == 2) ? 0 : pb + 1;

    while (true) {
        int acc[4][8][4];
#pragma unroll
        for (int mt = 0; mt < 4; mt++)
#pragma unroll
            for (int nt = 0; nt < 8; nt++)
#pragma unroll
                for (int c = 0; c < 4; c++) acc[mt][nt][c] = 0;

        for (int kc = 0; kc < NSTEPS; kc++) {
            if (kc < NSTEPS - 1) asm volatile("cp.async.wait_group 1;" ::: "memory");
            else                 asm volatile("cp.async.wait_group 0;" ::: "memory");
            __syncthreads();
            if (kc + 2 < NSTEPS) {
                load_stage(za, zb, kc + 2, pb);
                pb = (pb == 2) ? 0 : pb + 1;
            }
            const uint32_t sA = sbase + gb * STAGE_BYTES;
            const uint32_t sB = sA + TILE_BYTES;
            gb = (gb == 2) ? 0 : gb + 1;

#pragma unroll
            for (int ks = 0; ks < 2; ks++) {     // two k32 steps per 64B chunk
                uint32_t a[4][4];
#pragma unroll
                for (int mt = 0; mt < 4; mt++)
                    ldm_x4(a[mt][0], a[mt][1], a[mt][2], a[mt][3],
                           sA + swz(a_row + mt * 16, ks * 2 + a_chsel));
                uint32_t b[4][4];
#pragma unroll
                for (int p = 0; p < 4; p++)
                    ldm_x4(b[p][0], b[p][1], b[p][2], b[p][3],
                           sB + swz(b_row + p * 16, ks * 2 + b_chsel));
                // dense MMA burst, no smem ops interleaved
#pragma unroll
                for (int p = 0; p < 4; p++)
#pragma unroll
                    for (int mt = 0; mt < 4; mt++) {
                        mma_s8(acc[mt][p * 2],     a[mt], &b[p][0]);
                        mma_s8(acc[mt][p * 2 + 1], a[mt], &b[p][2]);
                    }
            }
        }

        // ---- prefetch next tile's first two stages (hides load latency behind epilogue)
        const int t2 = t + gridDim.x;
        int nti = ti, ntj = tj;
        const int8_t *nza = za, *nzb = zb;
        if (t2 < NTILES) {
            tile_of(t2, nti, ntj);
            nza = g_zq + (size_t)nti * BM * DIM;
            nzb = g_zq + (size_t)ntj * BN * DIM;
            load_stage(nza, nzb, 0, pb); pb = (pb == 2) ? 0 : pb + 1;
            load_stage(nza, nzb, 1, pb); pb = (pb == 2) ? 0 : pb + 1;
        }

        // ---------------- epilogue: dequant + exp + row/col sums ----------------
        const bool diag = (ti == tj);
        const int row0 = ti * BM + warp_m * 64 + (lane >> 2);
        const int col0 = tj * BN + warp_n * 64 + (lane & 3) * 2;
        float rs[4][2] = {{0.f,0.f},{0.f,0.f},{0.f,0.f},{0.f,0.f}};

        if (diag) {
#pragma unroll
            for (int mt = 0; mt < 4; mt++)
#pragma unroll
                for (int nt = 0; nt < 8; nt++)
#pragma unroll
                    for (int c = 0; c < 4; c++) {
                        int grow = row0 + mt * 16 + (c >> 1) * 8;
                        int gcol = col0 + nt * 8 + (c & 1);
                        float e = __expf((float)acc[mt][nt][c] * DEQ);
                        rs[mt][c >> 1] += (grow == gcol) ? 0.f : e;
                    }
        } else {
            float cs[8][2];
#pragma unroll
            for (int nt = 0; nt < 8; nt++) { cs[nt][0] = 0.f; cs[nt][1] = 0.f; }
#pragma unroll
            for (int mt = 0; mt < 4; mt++)
#pragma unroll
                for (int nt = 0; nt < 8; nt++)
#pragma unroll
                    for (int c = 0; c < 4; c++) {
                        float e = __expf((float)acc[mt][nt][c] * DEQ);
                        rs[mt][c >> 1] += e;
                        cs[nt][c & 1] += e;
                    }
#pragma unroll
            for (int o = 4; o <= 16; o <<= 1)
#pragma unroll
                for (int nt = 0; nt < 8; nt++) {
                    cs[nt][0] += __shfl_xor_sync(0xffffffffu, cs[nt][0], o);
                    cs[nt][1] += __shfl_xor_sync(0xffffffffu, cs[nt][1], o);
                }
            if (lane < 4) {
                const int cbase = tj * BN + warp_n * 64 + lane * 2;
#pragma unroll
                for (int nt = 0; nt < 8; nt++) {
                    atomicAdd(&g_rowsum[cbase + nt * 8],     cs[nt][0]);
                    atomicAdd(&g_rowsum[cbase + nt * 8 + 1], cs[nt][1]);
                }
            }
        }
#pragma unroll
        for (int o = 1; o <= 2; o <<= 1)
#pragma unroll
            for (int mt = 0; mt < 4; mt++)
#pragma unroll
                for (int h = 0; h < 2; h++)
                    rs[mt][h] += __shfl_xor_sync(0xffffffffu, rs[mt][h], o);
        if ((lane & 3) == 0) {
#pragma unroll
            for (int mt = 0; mt < 4; mt++)
#pragma unroll
                for (int h = 0; h < 2; h++)
                    atomicAdd(&g_rowsum[row0 + mt * 16 + h * 8], rs[mt][h]);
        }

        if (t2 >= NTILES) break;
        t = t2; ti = nti; tj = ntj; za = nza; zb = nzb;
    }
}

// ============ Kernel C: final reduction ============
__global__ void __launch_bounds__(1024) k_red(float* __restrict__ out) {
    __shared__ float sh[1024];
    const int t = threadIdx.x;
    float s = 0.f;
    for (int i = t; i < TWOB; i += 1024) s += logf(g_rowsum[i]);
    float p = 0.f;
    for (int i = t; i < BATCH; i += 1024) p += g_pos[i];
    sh[t] = s - 2.f * INV_TEMP * p;   // sum(lse) - sum(positive logits)
    __syncthreads();
    for (int o = 512; o; o >>= 1) {
        if (t < o) sh[t] += sh[t + o];
        __syncthreads();
    }
    if (!t) out[0] = sh[0] / (float)TWOB;
}

extern "C" void kernel_launch(void* const* d_in, const int* in_sizes, int n_in,
                              void* d_out, int out_size) {
    const float* p1 = (const float*)d_in[0];
    const float* p2 = (const float*)d_in[1];
    int nsm = 148;
    cudaDeviceGetAttribute(&nsm, cudaDevAttrMultiProcessorCount, 0);
    int grid = 2 * nsm;
    if (grid > NTILES) grid = NTILES;
    k_norm<<<BATCH, 128>>>(p1, p2);
    k_sim<<<grid, 128>>>();
    k_red<<<1, 1024>>>((float*)d_out);
}

// round 7
// speedup vs baseline: 2.7502x; 2.7502x over previous
#include <cuda_runtime.h>
#include <cuda_bf16.h>
#include <cstdint>

#define BATCH 4096
#define DIM 512
#define TWOB 8192
#define INV_TEMP 10.0f

// ---------------- scratch (no allocations allowed) ----------------
__device__ __nv_bfloat16 g_z[(size_t)TWOB * DIM];   // normalized rows, bf16 [8192,512]
__device__ float g_pos[BATCH];                      // cos(n1_i, n2_i)
__device__ float g_rowsum[TWOB];                    // sum_{j!=i} exp(cos_ij/T)

// ---------------- helpers ----------------
__device__ __forceinline__ uint32_t smem_u32(const void* p) {
    uint32_t a;
    asm("{ .reg .u64 t; cvta.to.shared.u64 t, %1; cvt.u32.u64 %0, t; }" : "=r"(a) : "l"(p));
    return a;
}
__device__ __forceinline__ void cp16(uint32_t s, const void* g) {
    asm volatile("cp.async.cg.shared.global [%0], [%1], 16;" :: "r"(s), "l"(g) : "memory");
}
__device__ __forceinline__ void ldm_x4(uint32_t& r0, uint32_t& r1, uint32_t& r2, uint32_t& r3,
                                       uint32_t addr) {
    asm volatile("ldmatrix.sync.aligned.m8n8.x4.shared.b16 {%0,%1,%2,%3}, [%4];"
                 : "=r"(r0), "=r"(r1), "=r"(r2), "=r"(r3) : "r"(addr));
}
__device__ __forceinline__ void mma_16816(float* d, const uint32_t* a, const uint32_t* b) {
    asm volatile(
        "mma.sync.aligned.m16n8k16.row.col.f32.bf16.bf16.f32 "
        "{%0,%1,%2,%3}, {%4,%5,%6,%7}, {%8,%9}, {%0,%1,%2,%3};"
        : "+f"(d[0]), "+f"(d[1]), "+f"(d[2]), "+f"(d[3])
        : "r"(a[0]), "r"(a[1]), "r"(a[2]), "r"(a[3]), "r"(b[0]), "r"(b[1]));
}

// tile geometry
#define BM 128
#define BN 128
#define BK 32
#define NSTEPS (DIM / BK)          // 16
#define NT (TWOB / BM)             // 64 tile-rows
#define NTILES (NT * (NT + 1) / 2) // 2080 upper-triangle tiles
#define TILE_BYTES (BM * BK * 2)   // 8192 per operand tile
#define STAGE_BYTES (2 * TILE_BYTES)
#define NSTAGE 4
#define SMEM_BYTES (NSTAGE * STAGE_BYTES)   // 64 KB dynamic

// swizzled byte offset inside a [rows x 32cols bf16] tile (64B rows, 4 x 16B chunks)
__device__ __forceinline__ uint32_t swz(int row, int chunk) {
    return (uint32_t)(row * 64 + ((chunk ^ ((row >> 1) & 3)) << 4));
}

// ============ Kernel A: L2-normalize rows, positives, zero rowsums ============
__global__ void __launch_bounds__(128) k_norm(const float* __restrict__ p1,
                                              const float* __restrict__ p2) {
    const int i = blockIdx.x;
    const int t = threadIdx.x, w = t >> 5, l = t & 31;
    __shared__ float red[8];

    float4 a = ((const float4*)(p1 + (size_t)i * DIM))[t];
    float4 b = ((const float4*)(p2 + (size_t)i * DIM))[t];
    float sa = a.x * a.x + a.y * a.y + a.z * a.z + a.w * a.w;
    float sb = b.x * b.x + b.y * b.y + b.z * b.z + b.w * b.w;
#pragma unroll
    for (int o = 16; o; o >>= 1) {
        sa += __shfl_xor_sync(0xffffffffu, sa, o);
        sb += __shfl_xor_sync(0xffffffffu, sb, o);
    }
    if (!l) { red[w] = sa; red[4 + w] = sb; }
    __syncthreads();
    sa = red[0] + red[1] + red[2] + red[3];
    sb = red[4] + red[5] + red[6] + red[7];
    const float ra = rsqrtf(fmaxf(sa, 1e-24f));
    const float rb = rsqrtf(fmaxf(sb, 1e-24f));
    float4 na = make_float4(a.x * ra, a.y * ra, a.z * ra, a.w * ra);
    float4 nb = make_float4(b.x * rb, b.y * rb, b.z * rb, b.w * rb);
    float dp = na.x * nb.x + na.y * nb.y + na.z * nb.z + na.w * nb.w;
#pragma unroll
    for (int o = 16; o; o >>= 1) dp += __shfl_xor_sync(0xffffffffu, dp, o);
    __syncthreads();
    if (!l) red[w] = dp;
    __syncthreads();
    if (!t) {
        g_pos[i] = red[0] + red[1] + red[2] + red[3];
        g_rowsum[i] = 0.f;
        g_rowsum[BATCH + i] = 0.f;
    }
    __nv_bfloat162* z1 = (__nv_bfloat162*)(g_z + (size_t)i * DIM);
    __nv_bfloat162* z2 = (__nv_bfloat162*)(g_z + (size_t)(BATCH + i) * DIM);
    z1[2 * t]     = __floats2bfloat162_rn(na.x, na.y);
    z1[2 * t + 1] = __floats2bfloat162_rn(na.z, na.w);
    z2[2 * t]     = __floats2bfloat162_rn(nb.x, nb.y);
    z2[2 * t + 1] = __floats2bfloat162_rn(nb.z, nb.w);
}

// ============ Kernel B: persistent upper-triangle bf16 GEMM + exp + row/col sums ============
// 4 warps (2x2), 64x64 warp tiles, 2 CTAs/SM, 4-stage pipeline.
// Producer runs exactly 3 stages ahead of consumer, crossing tile boundaries:
// epilogue + next-tile prologue fully hidden. wait_group 2 statically correct.
__global__ void __launch_bounds__(128, 2) k_sim() {
    extern __shared__ __align__(128) char smem[];
    const uint32_t sbase = smem_u32(smem);

    const int tid = threadIdx.x;
    const int lane = tid & 31;
    const int wid = tid >> 5;
    const int warp_m = wid & 1;
    const int warp_n = wid >> 1;

    auto tile_of = [](int bid, int& ti, int& tj) {
        auto offs = [](int t) { return t * NT - (t * (t - 1)) / 2; };
        int x = (int)((2.f * NT + 1.f -
                       sqrtf((2.f * NT + 1.f) * (2.f * NT + 1.f) - 8.f * bid)) * 0.5f);
        if (x < 0) x = 0;
        if (x > NT - 1) x = NT - 1;
        while (offs(x + 1) <= bid) x++;
        while (offs(x) > bid) x--;
        ti = x;
        tj = x + (bid - offs(x));
    };

    auto load_stage = [&](const __nv_bfloat16* pza, const __nv_bfloat16* pzb,
                          int kc, int buf) {
        const uint32_t sA = sbase + buf * STAGE_BYTES;
        const uint32_t sB = sA + TILE_BYTES;
#pragma unroll
        for (int it = 0; it < 8; it++) {
            int id = it * 128 + tid;
            int tile = id >> 9;
            int idx = id & 511;
            int row = idx >> 2, ch = idx & 3;
            const __nv_bfloat16* g = (tile ? pzb : pza) + (size_t)row * DIM + kc * BK + ch * 8;
            cp16((tile ? sB : sA) + swz(row, ch), g);
        }
        asm volatile("cp.async.commit_group;" ::: "memory");
    };

    // ldmatrix lane address components
    const int a_row = warp_m * 64 + (lane & 15);
    const int a_chsel = lane >> 4;
    const int b_row = warp_n * 64 + (lane & 7) + ((lane >> 4) << 3);
    const int b_chsel = (lane >> 3) & 1;

    int t = blockIdx.x;
    if (t >= NTILES) return;
    int ti, tj;
    tile_of(t, ti, tj);
    const __nv_bfloat16* za = g_z + (size_t)ti * BM * DIM;
    const __nv_bfloat16* zb = g_z + (size_t)tj * BN * DIM;

    int pbuf = 0, cbuf = 0;   // producer/consumer stage counters (mod NSTAGE)
    load_stage(za, zb, 0, 0);
    load_stage(za, zb, 1, 1);
    load_stage(za, zb, 2, 2);
    pbuf = 3;

    while (true) {
        // next tile (wrap for the final iteration: redundant loads, harmless)
        int t2 = t + gridDim.x;
        int nti, ntj;
        tile_of(t2 < NTILES ? t2 : t, nti, ntj);
        const __nv_bfloat16* nza = g_z + (size_t)nti * BM * DIM;
        const __nv_bfloat16* nzb = g_z + (size_t)ntj * BN * DIM;

        float acc[4][8][4];
#pragma unroll
        for (int mt = 0; mt < 4; mt++)
#pragma unroll
            for (int nt = 0; nt < 8; nt++)
#pragma unroll
                for (int c = 0; c < 4; c++) acc[mt][nt][c] = 0.f;

        for (int kc = 0; kc < NSTEPS; kc++) {
            asm volatile("cp.async.wait_group 2;" ::: "memory");
            __syncthreads();
            {   // producer: stage kc+3 (this tile or the next)
                int s = kc + 3;
                if (s < NSTEPS) load_stage(za, zb, s, pbuf & 3);
                else            load_stage(nza, nzb, s - NSTEPS, pbuf & 3);
                pbuf++;
            }
            const uint32_t sA = sbase + (cbuf & 3) * STAGE_BYTES;
            const uint32_t sB = sA + TILE_BYTES;
            cbuf++;

#pragma unroll
            for (int ks = 0; ks < 2; ks++) {
                uint32_t a[4][4];
#pragma unroll
                for (int mt = 0; mt < 4; mt++)
                    ldm_x4(a[mt][0], a[mt][1], a[mt][2], a[mt][3],
                           sA + swz(a_row + mt * 16, ks * 2 + a_chsel));
#pragma unroll
                for (int p = 0; p < 4; p++) {
                    uint32_t b[4];
                    ldm_x4(b[0], b[1], b[2], b[3],
                           sB + swz(b_row + p * 16, ks * 2 + b_chsel));
#pragma unroll
                    for (int mt = 0; mt < 4; mt++) {
                        mma_16816(acc[mt][p * 2],     a[mt], b);
                        mma_16816(acc[mt][p * 2 + 1], a[mt], b + 2);
                    }
                }
            }
        }

        // ---------------- epilogue: exp + row/col sums (producer already 3 ahead) ----
        const bool diag = (ti == tj);
        const int row0 = ti * BM + warp_m * 64 + (lane >> 2);
        const int col0 = tj * BN + warp_n * 64 + (lane & 3) * 2;
        float rs[4][2] = {{0.f,0.f},{0.f,0.f},{0.f,0.f},{0.f,0.f}};

        if (diag) {
#pragma unroll
            for (int mt = 0; mt < 4; mt++)
#pragma unroll
                for (int nt = 0; nt < 8; nt++)
#pragma unroll
                    for (int c = 0; c < 4; c++) {
                        int grow = row0 + mt * 16 + (c >> 1) * 8;
                        int gcol = col0 + nt * 8 + (c & 1);
                        float e = __expf(acc[mt][nt][c] * INV_TEMP);
                        rs[mt][c >> 1] += (grow == gcol) ? 0.f : e;
                    }
        } else {
            float cs[8][2];
#pragma unroll
            for (int nt = 0; nt < 8; nt++) { cs[nt][0] = 0.f; cs[nt][1] = 0.f; }
#pragma unroll
            for (int mt = 0; mt < 4; mt++)
#pragma unroll
                for (int nt = 0; nt < 8; nt++)
#pragma unroll
                    for (int c = 0; c < 4; c++) {
                        float e = __expf(acc[mt][nt][c] * INV_TEMP);
                        rs[mt][c >> 1] += e;
                        cs[nt][c & 1] += e;
                    }
#pragma unroll
            for (int o = 4; o <= 16; o <<= 1)
#pragma unroll
                for (int nt = 0; nt < 8; nt++) {
                    cs[nt][0] += __shfl_xor_sync(0xffffffffu, cs[nt][0], o);
                    cs[nt][1] += __shfl_xor_sync(0xffffffffu, cs[nt][1], o);
                }
            if (lane < 4) {
                const int cbase = tj * BN + warp_n * 64 + lane * 2;
#pragma unroll
                for (int nt = 0; nt < 8; nt++) {
                    atomicAdd(&g_rowsum[cbase + nt * 8],     cs[nt][0]);
                    atomicAdd(&g_rowsum[cbase + nt * 8 + 1], cs[nt][1]);
                }
            }
        }
#pragma unroll
        for (int o = 1; o <= 2; o <<= 1)
#pragma unroll
            for (int mt = 0; mt < 4; mt++)
#pragma unroll
                for (int h = 0; h < 2; h++)
                    rs[mt][h] += __shfl_xor_sync(0xffffffffu, rs[mt][h], o);
        if ((lane & 3) == 0) {
#pragma unroll
            for (int mt = 0; mt < 4; mt++)
#pragma unroll
                for (int h = 0; h < 2; h++)
                    atomicAdd(&g_rowsum[row0 + mt * 16 + h * 8], rs[mt][h]);
        }

        if (t2 >= NTILES) break;
        t = t2; ti = nti; tj = ntj; za = nza; zb = nzb;
    }
    asm volatile("cp.async.wait_group 0;" ::: "memory");
}

// ============ Kernel C: final reduction ============
__global__ void __launch_bounds__(1024) k_red(float* __restrict__ out) {
    __shared__ float sh[1024];
    const int t = threadIdx.x;
    float s = 0.f;
    for (int i = t; i < TWOB; i += 1024) s += logf(g_rowsum[i]);
    float p = 0.f;
    for (int i = t; i < BATCH; i += 1024) p += g_pos[i];
    sh[t] = s - 2.f * INV_TEMP * p;   // sum(lse) - sum(positive logits)
    __syncthreads();
    for (int o = 512; o; o >>= 1) {
        if (t < o) sh[t] += sh[t + o];
        __syncthreads();
    }
    if (!t) out[0] = sh[0] / (float)TWOB;
}

extern "C" void kernel_launch(void* const* d_in, const int* in_sizes, int n_in,
                              void* d_out, int out_size) {
    const float* p1 = (const float*)d_in[0];
    const float* p2 = (const float*)d_in[1];
    int nsm = 148;
    cudaDeviceGetAttribute(&nsm, cudaDevAttrMultiProcessorCount, 0);
    int grid = 2 * nsm;
    if (grid > NTILES) grid = NTILES;
    cudaFuncSetAttribute(k_sim, cudaFuncAttributeMaxDynamicSharedMemorySize, SMEM_BYTES);
    k_norm<<<BATCH, 128>>>(p1, p2);
    k_sim<<<grid, 128, SMEM_BYTES>>>();
    k_red<<<1, 1024>>>((float*)d_out);
}